// round 2
// baseline (speedup 1.0000x reference)
#include <cuda_runtime.h>

// Problem constants
#define AP 48        // paths
#define LL 64        // length
#define DD 64        // channels
#define MM 63        // L-1 (increments)
#define PER_GRAM (AP*AP)          // 2304
#define NPAIRS (3*PER_GRAM)       // 6912
#define INC_STRIDE (63*64)

// Static scratch (no allocation allowed)
__device__ float g_inc[(size_t)NPAIRS * INC_STRIDE];   // ~111.5 MB
__device__ float g_K[NPAIRS];

#define TILE_FLOATS (64 * 65)     // [d][i], stride 65, row 63 zero pad
#define SMEM_BYTES (4 * TILE_FLOATS * sizeof(float))   // 2 pairs x (A,B) = 66560 B

// ---------------------------------------------------------------------------
// Kernel 1: per-pair increment Gram  inc[i][j] = dX[a,i] . dY[b,j]
// 2 pairs per 128-thread CTA; 64 threads per pair; 8x8 register tile/thread.
// Thread (ty,tx): rows 8*ty..8*ty+7 (blocked), cols tx+8q (strided, q=0..7)
//   -> A reads broadcast, B reads conflict-free.
// ---------------------------------------------------------------------------
__global__ void __launch_bounds__(128) gemm_kernel(
    const float* __restrict__ X, const float* __restrict__ Y)
{
    extern __shared__ float smem[];

    const int half = threadIdx.x >> 6;          // pair slot within CTA
    const int t    = threadIdx.x & 63;
    const int pid  = blockIdx.x * 2 + half;

    const int gram = pid / PER_GRAM;
    const int r    = pid % PER_GRAM;
    const int a    = r / AP, b = r % AP;
    const bool active = (gram == 2) || (a <= b);

    float* sA = smem + half * (2 * TILE_FLOATS);
    float* sB = sA + TILE_FLOATS;

    if (active) {
        const float* __restrict__ P = (gram == 1) ? Y : X;
        const float* __restrict__ Q = (gram == 0) ? X : Y;
        const float* pa = P + a * (LL * DD);
        const float* qb = Q + b * (LL * DD);

        // load increments, transposed [d][i], stride 65 (conflict-free STS)
        for (int idx = t; idx < 64 * 64; idx += 64) {
            const int i = idx >> 6;     // 0..63 (63 = zero pad row)
            const int d = idx & 63;
            float va = 0.0f, vb = 0.0f;
            if (i < MM) {
                va = pa[(i + 1) * DD + d] - pa[i * DD + d];
                vb = qb[(i + 1) * DD + d] - qb[i * DD + d];
            }
            sA[d * 65 + i] = va;
            sB[d * 65 + i] = vb;
        }
    }
    __syncthreads();
    if (!active) return;

    const int ty = t >> 3;              // 0..7
    const int tx = t & 7;               // 0..7
    const int i0 = ty * 8;

    float acc[8][8];
#pragma unroll
    for (int k = 0; k < 8; k++)
#pragma unroll
        for (int q = 0; q < 8; q++) acc[k][q] = 0.0f;

    const float* sA_ = sA + i0;
    const float* sB_ = sB + tx;

#pragma unroll 4
    for (int d = 0; d < 64; d++) {
        float av[8], bv[8];
#pragma unroll
        for (int k = 0; k < 8; k++) av[k] = sA_[d * 65 + k];
#pragma unroll
        for (int q = 0; q < 8; q++) bv[q] = sB_[d * 65 + 8 * q];
#pragma unroll
        for (int k = 0; k < 8; k++)
#pragma unroll
            for (int q = 0; q < 8; q++)
                acc[k][q] = fmaf(av[k], bv[q], acc[k][q]);
    }

    float* out = g_inc + (size_t)pid * INC_STRIDE;
#pragma unroll
    for (int k = 0; k < 8; k++) {
        const int i = i0 + k;
        if (i < MM) {
#pragma unroll
            for (int q = 0; q < 8; q++)
                out[i * 64 + tx + 8 * q] = acc[k][q];
        }
    }
}

// ---------------------------------------------------------------------------
// Kernel 2: Goursat PDE recursion, one warp per pair, with row prefetch.
// Row update is a prefix sum: new[j+1] = 1 + sum_{k<=j} c[k],
//   c[j] = prev[j+1] + prev[j]*(inc[i,j]-1).
// ---------------------------------------------------------------------------
__global__ void __launch_bounds__(256) pde_kernel()
{
    const int warp = (blockIdx.x * blockDim.x + threadIdx.x) >> 5;
    const int lane = threadIdx.x & 31;
    if (warp >= NPAIRS) return;

    const int p = warp;
    const int gram = p / PER_GRAM;
    const int r = p % PER_GRAM;
    const int a = r / AP, b = r % AP;

    if (gram < 2 && a > b) {               // mirrored pair handled via weight 2
        if (lane == 0) g_K[p] = 0.0f;
        return;
    }

    float w;
    if (gram == 2) w = -2.0f / (float)PER_GRAM;
    else           w = ((a == b) ? 1.0f : 2.0f) / (float)PER_GRAM;

    const float* __restrict__ base = g_inc + (size_t)p * INC_STRIDE + 2 * lane;
    const bool last = (lane == 31);

    float prev0 = 1.0f;   // K[i][2l]
    float prev1 = 1.0f;   // K[i][2l+1]

    float2 inc = *reinterpret_cast<const float2*>(base);

    for (int i = 0; i < MM; i++) {
        float2 nxt = make_float2(0.0f, 0.0f);
        if (i + 1 < MM)
            nxt = *reinterpret_cast<const float2*>(base + (i + 1) * 64);

        const float prev2 = __shfl_down_sync(0xffffffffu, prev0, 1); // K[i][2l+2]

        const float c0 = fmaf(prev0, inc.x - 1.0f, prev1);
        const float c1 = last ? 0.0f : fmaf(prev1, inc.y - 1.0f, prev2);

        const float s = c0 + c1;
        float tcum = s;
#pragma unroll
        for (int off = 1; off < 32; off <<= 1) {
            const float u = __shfl_up_sync(0xffffffffu, tcum, off);
            if (lane >= off) tcum += u;
        }
        const float E = tcum - s;         // exclusive scan of pair sums

        prev0 = 1.0f + E;                 // new K[i+1][2l]
        prev1 = prev0 + c0;               // new K[i+1][2l+1]
        inc = nxt;
    }

    if (last) g_K[p] = w * prev1;         // K[63][63], weighted
}

// ---------------------------------------------------------------------------
// Kernel 3: deterministic final reduction + mean((X0 - Y0)^2)
// ---------------------------------------------------------------------------
__global__ void __launch_bounds__(1024) reduce_kernel(
    const float* __restrict__ X, const float* __restrict__ Y,
    float* __restrict__ out)
{
    __shared__ float sdata[1024];
    const int tid = threadIdx.x;

    float s = 0.0f;
    for (int p = tid; p < NPAIRS; p += 1024) s += g_K[p];

    float s2 = 0.0f;
    for (int idx = tid; idx < AP * DD; idx += 1024) {
        const int aa = idx >> 6;
        const int d  = idx & 63;
        const float diff = X[aa * (LL * DD) + d] - Y[aa * (LL * DD) + d];
        s2 = fmaf(diff, diff, s2);
    }
    s += s2 * (1.0f / (float)(AP * DD));

    sdata[tid] = s;
    __syncthreads();
    for (int k = 512; k > 0; k >>= 1) {
        if (tid < k) sdata[tid] += sdata[tid + k];
        __syncthreads();
    }
    if (tid == 0) out[0] = sdata[0];
}

// ---------------------------------------------------------------------------
extern "C" void kernel_launch(void* const* d_in, const int* in_sizes, int n_in,
                              void* d_out, int out_size)
{
    const float* X = (const float*)d_in[0];
    const float* Y = (const float*)d_in[1];
    float* out = (float*)d_out;

    static bool attr_done = false;
    if (!attr_done) {
        cudaFuncSetAttribute(gemm_kernel,
                             cudaFuncAttributeMaxDynamicSharedMemorySize,
                             SMEM_BYTES);
        attr_done = true;
    }

    gemm_kernel<<<NPAIRS / 2, 128, SMEM_BYTES>>>(X, Y);
    pde_kernel<<<(NPAIRS * 32) / 256, 256>>>();
    reduce_kernel<<<1, 1024>>>(X, Y, out);
}

// round 3
// speedup vs baseline: 1.4113x; 1.4113x over previous
#include <cuda_runtime.h>

// Problem constants
#define AP 48        // paths
#define LL 64        // length
#define DD 64        // channels
#define MM 63        // L-1 (increments)
#define PER_GRAM (AP*AP)          // 2304
#define NPAIRS (3*PER_GRAM)       // 6912

#define NBLK 96                   // 48 X path-blocks + 48 Y path-blocks
#define ROWS (NBLK*64)            // 6144 padded rows (row 63 of each block = 0)
#define NTILE 48                  // 6144 / 128 tiles per dim
#define NTRI (NTILE*(NTILE+1)/2)  // 1176 upper-triangle tiles

// Static scratch (no allocation allowed)
__device__ float g_dZ[(size_t)ROWS * 64];          // 1.5 MB  padded increments
__device__ float g_G[(size_t)ROWS * ROWS];         // 151 MB  big Gram
__device__ float g_K[NPAIRS];

// smem strides (bank-conflict analysis in comments)
#define SA_STRIDE 129   // A^T [k][m], scalar reads -> banks (k+m)%32 distinct
#define SB_STRIDE 130   // B^T [k][n], 8B-aligned float2 reads, conflict-free
#define SMEM_FLOATS (64*SA_STRIDE + 64*SB_STRIDE)
#define SMEM_BYTES (SMEM_FLOATS * sizeof(float))   // 66,304 B

// ---------------------------------------------------------------------------
// Kernel 0: build padded increments dZ[blk*64 + i][d]
//   blk < 48: X increments; blk >= 48: Y increments; row i = 63 zeroed.
// ---------------------------------------------------------------------------
__global__ void __launch_bounds__(256) dz_kernel(
    const float* __restrict__ X, const float* __restrict__ Y)
{
    const int blk = blockIdx.x;
    const float* src = (blk < AP) ? (X + blk * (LL * DD))
                                  : (Y + (blk - AP) * (LL * DD));
    float* dst = g_dZ + (size_t)blk * (64 * DD);
    for (int idx = threadIdx.x; idx < 64 * DD; idx += 256) {
        const int i = idx >> 6;
        const int d = idx & 63;
        float v = 0.0f;
        if (i < MM) v = src[(i + 1) * DD + d] - src[i * DD + d];
        dst[idx] = v;
    }
}

// ---------------------------------------------------------------------------
// Kernel 1: G = dZ * dZ^T, 128x128x64 tiles, upper triangle (u >= t).
// 256 threads = 16x16; thread (ty,tx) owns rows 8*ty..+7 (blocked) and
// column pairs {2*tx + 32*j, +1} for j=0..3 (strided), via packed fma.rn.f32x2.
// ---------------------------------------------------------------------------
__global__ void __launch_bounds__(256, 2) gemm_kernel()
{
    extern __shared__ float smem[];
    float* sA = smem;                       // [64][SA_STRIDE]  A^T: sA[k][m]
    float* sB = smem + 64 * SA_STRIDE;      // [64][SB_STRIDE]  B^T: sB[k][n]

    // decode triangular tile index -> (t, u), u >= t
    int q = blockIdx.x;
    int t = 0;
    while (q >= NTILE - t) { q -= NTILE - t; t++; }
    const int u = t + q;

    const int gr0 = t * 128;   // global row base (A side)
    const int gc0 = u * 128;   // global col base (B side)
    const int tid = threadIdx.x;

    // load tiles: idx -> (m, k), consecutive tid = consecutive k (coalesced)
    for (int idx = tid; idx < 128 * 64; idx += 256) {
        const int m = idx >> 6;
        const int k = idx & 63;
        sA[k * SA_STRIDE + m] = g_dZ[(size_t)(gr0 + m) * 64 + k];
        sB[k * SB_STRIDE + m] = g_dZ[(size_t)(gc0 + m) * 64 + k];
    }
    __syncthreads();

    const int ty = tid >> 4;     // 0..15
    const int tx = tid & 15;     // 0..15
    const int m0 = ty * 8;
    const int n0 = 2 * tx;

    unsigned long long acc[8][4];
#pragma unroll
    for (int i = 0; i < 8; i++)
#pragma unroll
        for (int j = 0; j < 4; j++) acc[i][j] = 0ull;

    const float* sA_ = sA + m0;
    const float* sB_ = sB + n0;

#pragma unroll 8
    for (int k = 0; k < 64; k++) {
        unsigned long long aa[8], bb[4];
#pragma unroll
        for (int i = 0; i < 8; i++) {
            const float a = sA_[k * SA_STRIDE + i];
            asm("mov.b64 %0, {%1, %1};" : "=l"(aa[i]) : "f"(a));
        }
#pragma unroll
        for (int j = 0; j < 4; j++)
            bb[j] = *reinterpret_cast<const unsigned long long*>(
                        &sB_[k * SB_STRIDE + 32 * j]);
#pragma unroll
        for (int i = 0; i < 8; i++)
#pragma unroll
            for (int j = 0; j < 4; j++)
                asm("fma.rn.f32x2 %0, %1, %2, %0;"
                    : "+l"(acc[i][j]) : "l"(aa[i]), "l"(bb[j]));
    }

    // epilogue: store float2s, 16 lanes -> 128B contiguous
#pragma unroll
    for (int i = 0; i < 8; i++) {
        float* row = g_G + (size_t)(gr0 + m0 + i) * ROWS + gc0 + n0;
#pragma unroll
        for (int j = 0; j < 4; j++) {
            float lo, hi;
            asm("mov.b64 {%0, %1}, %2;" : "=f"(lo), "=f"(hi) : "l"(acc[i][j]));
            *reinterpret_cast<float2*>(row + 32 * j) = make_float2(lo, hi);
        }
    }
}

// ---------------------------------------------------------------------------
// Kernel 2: Goursat PDE recursion, one warp per pair, reading from g_G.
// Row update is a prefix sum: new[j+1] = 1 + sum_{k<=j} c[k],
//   c[j] = prev[j+1] + prev[j]*(inc[i,j]-1).
// ---------------------------------------------------------------------------
__global__ void __launch_bounds__(256) pde_kernel()
{
    const int warp = (blockIdx.x * blockDim.x + threadIdx.x) >> 5;
    const int lane = threadIdx.x & 31;
    if (warp >= NPAIRS) return;

    const int p = warp;
    const int gram = p / PER_GRAM;
    const int r = p % PER_GRAM;
    const int a = r / AP, b = r % AP;

    if (gram < 2 && a > b) {               // mirrored pair handled via weight 2
        if (lane == 0) g_K[p] = 0.0f;
        return;
    }

    float w;
    int pa, pb;
    if (gram == 2) { w = -2.0f / (float)PER_GRAM; pa = a;          pb = AP + b; }
    else if (gram == 1) { w = ((a == b) ? 1.0f : 2.0f) / (float)PER_GRAM;
                          pa = AP + a;     pb = AP + b; }
    else           { w = ((a == b) ? 1.0f : 2.0f) / (float)PER_GRAM;
                          pa = a;          pb = b; }

    const float* __restrict__ base =
        g_G + (size_t)(64 * pa) * ROWS + 64 * pb + 2 * lane;
    const bool last = (lane == 31);

    float prev0 = 1.0f;   // K[i][2l]
    float prev1 = 1.0f;   // K[i][2l+1]

    float2 inc = __ldg(reinterpret_cast<const float2*>(base));

    for (int i = 0; i < MM; i++) {
        float2 nxt = make_float2(0.0f, 0.0f);
        if (i + 1 < MM)
            nxt = __ldg(reinterpret_cast<const float2*>(base + (size_t)(i + 1) * ROWS));

        const float prev2 = __shfl_down_sync(0xffffffffu, prev0, 1); // K[i][2l+2]

        const float c0 = fmaf(prev0, inc.x - 1.0f, prev1);
        const float c1 = last ? 0.0f : fmaf(prev1, inc.y - 1.0f, prev2);

        const float s = c0 + c1;
        float tcum = s;
#pragma unroll
        for (int off = 1; off < 32; off <<= 1) {
            const float uu = __shfl_up_sync(0xffffffffu, tcum, off);
            if (lane >= off) tcum += uu;
        }
        const float E = tcum - s;         // exclusive scan of pair sums

        prev0 = 1.0f + E;                 // new K[i+1][2l]
        prev1 = prev0 + c0;               // new K[i+1][2l+1]
        inc = nxt;
    }

    if (last) g_K[p] = w * prev1;         // K[63][63], weighted
}

// ---------------------------------------------------------------------------
// Kernel 3: deterministic final reduction + mean((X0 - Y0)^2)
// ---------------------------------------------------------------------------
__global__ void __launch_bounds__(1024) reduce_kernel(
    const float* __restrict__ X, const float* __restrict__ Y,
    float* __restrict__ out)
{
    __shared__ float sdata[1024];
    const int tid = threadIdx.x;

    float s = 0.0f;
    for (int p = tid; p < NPAIRS; p += 1024) s += g_K[p];

    float s2 = 0.0f;
    for (int idx = tid; idx < AP * DD; idx += 1024) {
        const int aa = idx >> 6;
        const int d  = idx & 63;
        const float diff = X[aa * (LL * DD) + d] - Y[aa * (LL * DD) + d];
        s2 = fmaf(diff, diff, s2);
    }
    s += s2 * (1.0f / (float)(AP * DD));

    sdata[tid] = s;
    __syncthreads();
    for (int k = 512; k > 0; k >>= 1) {
        if (tid < k) sdata[tid] += sdata[tid + k];
        __syncthreads();
    }
    if (tid == 0) out[0] = sdata[0];
}

// ---------------------------------------------------------------------------
extern "C" void kernel_launch(void* const* d_in, const int* in_sizes, int n_in,
                              void* d_out, int out_size)
{
    const float* X = (const float*)d_in[0];
    const float* Y = (const float*)d_in[1];
    float* out = (float*)d_out;

    static bool attr_done = false;
    if (!attr_done) {
        cudaFuncSetAttribute(gemm_kernel,
                             cudaFuncAttributeMaxDynamicSharedMemorySize,
                             SMEM_BYTES);
        attr_done = true;
    }

    dz_kernel<<<NBLK, 256>>>(X, Y);
    gemm_kernel<<<NTRI, 256, SMEM_BYTES>>>();
    pde_kernel<<<(NPAIRS * 32 + 255) / 256, 256>>>();
    reduce_kernel<<<1, 1024>>>(X, Y, out);
}